// round 1
// baseline (speedup 1.0000x reference)
#include <cuda_runtime.h>
#include <mma.h>
#include <math.h>

using namespace nvcuda;

#define H        128
#define BM       128      // rows (edges/nodes) per CTA
#define XLD      136      // padded leading dim for activation tile
#define WLD      136      // padded leading dim for weight tile
#define NTHREADS 256
#define MAX_NODES 100000
#define SMEM_BYTES (3 * BM * XLD * 4)

// ---------------- scratch (static device arrays; no allocation) ----------------
__device__ int   g_is64;
__device__ float g_A_src[(size_t)MAX_NODES * H];   // per-node: enc_p @ W1p^T
__device__ float g_A_dst[(size_t)MAX_NODES * H];   // per-node: enc_c @ W1c^T

// ---------------- runtime int32/int64 edge-index detection ----------------
// int64 values < 2^31 => int32 view has zeros at every odd word.
__global__ void detect_idx_kernel(const int* __restrict__ ei)
{
    int allz = 1;
    #pragma unroll
    for (int i = 1; i < 128; i += 2)
        if (ei[i] != 0) { allz = 0; break; }
    g_is64 = allz;
}

// ---------------- shared GEMM helpers (128x128x128, TF32 wmma) ----------------
// 8 warps: warp w covers M rows [wm, wm+32), N cols [wn, wn+64)
__device__ __forceinline__ void gemm128(
    const float* __restrict__ Xs, const float* __restrict__ Ws,
    wmma::fragment<wmma::accumulator, 16, 16, 8, float> (&acc)[2][4],
    int wm, int wn)
{
    #pragma unroll
    for (int i = 0; i < 2; i++)
        #pragma unroll
        for (int j = 0; j < 4; j++)
            wmma::fill_fragment(acc[i][j], 0.0f);

    #pragma unroll
    for (int k0 = 0; k0 < H; k0 += 8) {
        wmma::fragment<wmma::matrix_a, 16, 16, 8, wmma::precision::tf32, wmma::row_major> a[2];
        wmma::fragment<wmma::matrix_b, 16, 16, 8, wmma::precision::tf32, wmma::col_major> b[4];
        #pragma unroll
        for (int i = 0; i < 2; i++)
            wmma::load_matrix_sync(a[i], Xs + (wm + i * 16) * XLD + k0, XLD);
        #pragma unroll
        for (int j = 0; j < 4; j++)
            wmma::load_matrix_sync(b[j], Ws + (wn + j * 16) * WLD + k0, WLD);
        #pragma unroll
        for (int i = 0; i < 2; i++)
            #pragma unroll
            for (int j = 0; j < 4; j++)
                wmma::mma_sync(acc[i][j], a[i], b[j], acc[i][j]);
    }
}

__device__ __forceinline__ void store_acc(
    float* __restrict__ Xs,
    wmma::fragment<wmma::accumulator, 16, 16, 8, float> (&acc)[2][4],
    int wm, int wn)
{
    #pragma unroll
    for (int i = 0; i < 2; i++)
        #pragma unroll
        for (int j = 0; j < 4; j++)
            wmma::store_matrix_sync(Xs + (wm + i * 16) * XLD + wn + j * 16,
                                    acc[i][j], XLD, wmma::mem_row_major);
}

// ---------------- node precompute: A[n] = (leakyrelu(x W_enc^T + b_enc)) @ W1slab^T ----
__global__ void __launch_bounds__(NTHREADS, 1)
node_kernel(const float* __restrict__ x,
            const float* __restrict__ Wenc, const float* __restrict__ benc,
            const float* __restrict__ W1, int koff,
            int which_out, int n_nodes)
{
    extern __shared__ float sm[];
    float* Xs  = sm;
    float* Ws  = sm +     BM * XLD;   // encoder weights, col-view (k,j)->[j*WLD+k]
    float* W1s = sm + 2 * BM * XLD;   // W1 slab

    const int tid = threadIdx.x;
    const int n0  = blockIdx.x * BM;
    float* Aout = which_out ? g_A_dst : g_A_src;

    for (int idx = tid; idx < H * H; idx += NTHREADS) {
        int j = idx >> 7, k = idx & 127;
        Ws [j * WLD + k] = wmma::__float_to_tf32(Wenc[j * H + k]);
        W1s[j * WLD + k] = wmma::__float_to_tf32(W1[j * 3 * H + koff + k]);
    }
    for (int idx = tid; idx < BM * H; idx += NTHREADS) {
        int m = idx >> 7, j = idx & 127;
        int n = n0 + m; if (n >= n_nodes) n = n_nodes - 1;
        Xs[m * XLD + j] = wmma::__float_to_tf32(x[(size_t)n * H + j]);
    }
    __syncthreads();

    const int w  = tid >> 5;
    const int wm = (w & 3) * 32;
    const int wn = (w >> 2) * 64;
    wmma::fragment<wmma::accumulator, 16, 16, 8, float> acc[2][4];

    // stage 1: encoder
    gemm128(Xs, Ws, acc, wm, wn);
    __syncthreads();
    store_acc(Xs, acc, wm, wn);
    __syncthreads();
    for (int idx = tid; idx < BM * H; idx += NTHREADS) {
        int m = idx >> 7, j = idx & 127;
        float v = Xs[m * XLD + j] + benc[j];
        v = (v > 0.0f) ? v : 0.01f * v;        // LeakyReLU(0.01)
        Xs[m * XLD + j] = wmma::__float_to_tf32(v);
    }
    __syncthreads();

    // stage 2: W1 slab
    gemm128(Xs, W1s, acc, wm, wn);
    __syncthreads();
    store_acc(Xs, acc, wm, wn);
    __syncthreads();
    for (int idx = tid; idx < BM * H; idx += NTHREADS) {
        int m = idx >> 7, j = idx & 127;
        int n = n0 + m;
        if (n < n_nodes) Aout[(size_t)n * H + j] = Xs[m * XLD + j];
    }
}

// ---------------- edge kernel ----------------
// out[e] = relu(|par-cld| @ W1d^T + A_src[s] + A_dst[d] + b1) @ W2^T + b2
__global__ void __launch_bounds__(NTHREADS, 1)
edge_kernel(const float* __restrict__ x_src, const float* __restrict__ x_dst,
            const void* __restrict__ ei,
            const float* __restrict__ W1, const float* __restrict__ b1,
            const float* __restrict__ W2, const float* __restrict__ b2,
            float* __restrict__ out, int n_edges)
{
    extern __shared__ float sm[];
    float* Xs  = sm;
    float* W1s = sm +     BM * XLD;   // W1d slab (koff=256)
    float* W2s = sm + 2 * BM * XLD;
    __shared__ int s_si[BM], s_di[BM];

    const int tid = threadIdx.x;
    const int e0  = blockIdx.x * BM;
    const int is64 = g_is64;

    if (tid < BM) {
        int e = e0 + tid; if (e >= n_edges) e = n_edges - 1;
        long long si, di;
        if (is64) {
            si = ((const long long*)ei)[e];
            di = ((const long long*)ei)[(size_t)n_edges + e];
        } else {
            si = ((const int*)ei)[e];
            di = ((const int*)ei)[(size_t)n_edges + e];
        }
        s_si[tid] = (int)si;
        s_di[tid] = (int)di;
    }
    for (int idx = tid; idx < H * H; idx += NTHREADS) {
        int j = idx >> 7, k = idx & 127;
        W1s[j * WLD + k] = wmma::__float_to_tf32(W1[j * 3 * H + 2 * H + k]);
        W2s[j * WLD + k] = wmma::__float_to_tf32(W2[j * H + k]);
    }
    __syncthreads();

    // diff gather
    for (int idx = tid; idx < BM * H; idx += NTHREADS) {
        int m = idx >> 7, j = idx & 127;
        float p = x_src[(size_t)s_si[m] * H + j];
        float c = x_dst[(size_t)s_di[m] * H + j];
        Xs[m * XLD + j] = wmma::__float_to_tf32(fabsf(p - c));
    }
    __syncthreads();

    const int w  = tid >> 5;
    const int wm = (w & 3) * 32;
    const int wn = (w >> 2) * 64;
    wmma::fragment<wmma::accumulator, 16, 16, 8, float> acc[2][4];

    // stage 1: diff @ W1d^T
    gemm128(Xs, W1s, acc, wm, wn);
    __syncthreads();
    store_acc(Xs, acc, wm, wn);
    __syncthreads();
    for (int idx = tid; idx < BM * H; idx += NTHREADS) {
        int m = idx >> 7, j = idx & 127;
        float v = Xs[m * XLD + j]
                + g_A_src[(size_t)s_si[m] * H + j]
                + g_A_dst[(size_t)s_di[m] * H + j]
                + b1[j];
        v = fmaxf(v, 0.0f);                    // ReLU
        Xs[m * XLD + j] = wmma::__float_to_tf32(v);
    }
    __syncthreads();

    // stage 2: hidden @ W2^T
    gemm128(Xs, W2s, acc, wm, wn);
    __syncthreads();
    store_acc(Xs, acc, wm, wn);
    __syncthreads();
    for (int idx = tid; idx < BM * H; idx += NTHREADS) {
        int m = idx >> 7, j = idx & 127;
        int e = e0 + m;
        if (e < n_edges) out[(size_t)e * H + j] = Xs[m * XLD + j] + b2[j];
    }
}

// ---------------- launch ----------------
extern "C" void kernel_launch(void* const* d_in, const int* in_sizes, int n_in,
                              void* d_out, int out_size)
{
    const float* x_src = (const float*)d_in[0];
    const float* x_dst = (const float*)d_in[1];
    const void*  ei    = d_in[2];
    const float* Wp    = (const float*)d_in[3];
    const float* bp    = (const float*)d_in[4];
    const float* Wc    = (const float*)d_in[5];
    const float* bc    = (const float*)d_in[6];
    const float* W1    = (const float*)d_in[7];
    const float* b1    = (const float*)d_in[8];
    const float* W2    = (const float*)d_in[9];
    const float* b2    = (const float*)d_in[10];

    const int n_nodes = in_sizes[0] / H;
    const int n_edges = in_sizes[2] / 2;

    cudaFuncSetAttribute(node_kernel, cudaFuncAttributeMaxDynamicSharedMemorySize, SMEM_BYTES);
    cudaFuncSetAttribute(edge_kernel, cudaFuncAttributeMaxDynamicSharedMemorySize, SMEM_BYTES);

    detect_idx_kernel<<<1, 1>>>((const int*)ei);

    const int node_blocks = (n_nodes + BM - 1) / BM;
    node_kernel<<<node_blocks, NTHREADS, SMEM_BYTES>>>(x_src, Wp, bp, W1, 0, 0, n_nodes);
    node_kernel<<<node_blocks, NTHREADS, SMEM_BYTES>>>(x_dst, Wc, bc, W1, H, 1, n_nodes);

    const int edge_blocks = (n_edges + BM - 1) / BM;
    edge_kernel<<<edge_blocks, NTHREADS, SMEM_BYTES>>>(
        x_src, x_dst, ei, W1, b1, W2, b2, (float*)d_out, n_edges);
}

// round 2
// speedup vs baseline: 1.7161x; 1.7161x over previous
#include <cuda_runtime.h>
#include <mma.h>
#include <math.h>

using namespace nvcuda;

#define H        128
#define BM       128      // rows per tile
#define XLD      132      // padded leading dim (floats)
#define WLD      132
#define NTHREADS 512      // 16 warps
#define MAX_NODES 100000
#define NSM      152
#define SMEM_BYTES ((BM * XLD + 2 * H * WLD) * 4)

// ---------------- scratch ----------------
__device__ int   g_is64;
__device__ float g_A_src[(size_t)MAX_NODES * H];
__device__ float g_A_dst[(size_t)MAX_NODES * H];

// ---------------- int32/int64 detection ----------------
__global__ void detect_idx_kernel(const int* __restrict__ ei)
{
    int allz = 1;
    #pragma unroll
    for (int i = 1; i < 128; i += 2)
        if (ei[i] != 0) { allz = 0; break; }
    g_is64 = allz;
}

// ---------------- helpers ----------------
__device__ __forceinline__ float4 tf32x4(float4 v)
{
    v.x = wmma::__float_to_tf32(v.x);
    v.y = wmma::__float_to_tf32(v.y);
    v.z = wmma::__float_to_tf32(v.z);
    v.w = wmma::__float_to_tf32(v.w);
    return v;
}

// 16 warps: warp w -> M rows [wm,wm+32), N cols [wn,wn+32)
__device__ __forceinline__ void gemm128(
    const float* __restrict__ Xs, const float* __restrict__ Ws,
    wmma::fragment<wmma::accumulator, 16, 16, 8, float> (&acc)[2][2],
    int wm, int wn)
{
    #pragma unroll
    for (int i = 0; i < 2; i++)
        #pragma unroll
        for (int j = 0; j < 2; j++)
            wmma::fill_fragment(acc[i][j], 0.0f);

    #pragma unroll
    for (int k0 = 0; k0 < H; k0 += 8) {
        wmma::fragment<wmma::matrix_a, 16, 16, 8, wmma::precision::tf32, wmma::row_major> a[2];
        wmma::fragment<wmma::matrix_b, 16, 16, 8, wmma::precision::tf32, wmma::col_major> b[2];
        #pragma unroll
        for (int i = 0; i < 2; i++)
            wmma::load_matrix_sync(a[i], Xs + (wm + i * 16) * XLD + k0, XLD);
        #pragma unroll
        for (int j = 0; j < 2; j++)
            wmma::load_matrix_sync(b[j], Ws + (wn + j * 16) * WLD + k0, WLD);
        #pragma unroll
        for (int i = 0; i < 2; i++)
            #pragma unroll
            for (int j = 0; j < 2; j++)
                wmma::mma_sync(acc[i][j], a[i], b[j], acc[i][j]);
    }
}

__device__ __forceinline__ void store_acc(
    float* __restrict__ Xs,
    wmma::fragment<wmma::accumulator, 16, 16, 8, float> (&acc)[2][2],
    int wm, int wn)
{
    #pragma unroll
    for (int i = 0; i < 2; i++)
        #pragma unroll
        for (int j = 0; j < 2; j++)
            wmma::store_matrix_sync(Xs + (wm + i * 16) * XLD + wn + j * 16,
                                    acc[i][j], XLD, wmma::mem_row_major);
}

// ---------------- node precompute (persistent) ----------------
// A[n] = (leakyrelu(x @ Wenc^T + benc)) @ W1slab^T
__global__ void __launch_bounds__(NTHREADS, 1)
node_kernel(const float* __restrict__ x,
            const float* __restrict__ Wenc, const float* __restrict__ benc,
            const float* __restrict__ W1, int koff,
            float* __restrict__ Aout, int n_nodes, int ntiles)
{
    extern __shared__ float sm[];
    float* Xs  = sm;
    float* Ws  = sm + BM * XLD;
    float* W1s = sm + BM * XLD + H * WLD;

    const int tid = threadIdx.x;
    const int w   = tid >> 5;
    const int wm  = (w & 3) * 32;
    const int wn  = (w >> 2) * 32;

    // weights once per CTA (float4 loads; rows H=128 floats, W1 rows 3H=384 floats)
    for (int idx = tid; idx < H * (H / 4); idx += NTHREADS) {
        int j = idx >> 5, k4 = idx & 31;
        float4 we = __ldg((const float4*)(Wenc + (size_t)j * H) + k4);
        float4 w1 = __ldg((const float4*)(W1 + (size_t)j * 3 * H + koff) + k4);
        *(float4*)(Ws  + j * WLD + k4 * 4) = tf32x4(we);
        *(float4*)(W1s + j * WLD + k4 * 4) = tf32x4(w1);
    }

    const float4* x4 = (const float4*)x;
    const float4* b4 = (const float4*)benc;
    float4*       A4 = (float4*)Aout;

    wmma::fragment<wmma::accumulator, 16, 16, 8, float> acc[2][2];

    for (int t = blockIdx.x; t < ntiles; t += gridDim.x) {
        const int n0 = t * BM;
        __syncthreads();   // protect Xs reuse from previous iteration

        // load X tile
        #pragma unroll
        for (int it = 0; it < BM * H / 4 / NTHREADS; it++) {
            int idx4 = tid + it * NTHREADS;
            int m = idx4 >> 5, j4 = idx4 & 31;
            int n = n0 + m; if (n >= n_nodes) n = n_nodes - 1;
            float4 v = __ldg(x4 + (size_t)n * 32 + j4);
            *(float4*)(Xs + m * XLD + j4 * 4) = tf32x4(v);
        }
        __syncthreads();

        gemm128(Xs, Ws, acc, wm, wn);
        __syncthreads();
        store_acc(Xs, acc, wm, wn);
        __syncthreads();

        // LeakyReLU epilogue
        #pragma unroll
        for (int it = 0; it < BM * H / 4 / NTHREADS; it++) {
            int idx4 = tid + it * NTHREADS;
            int m = idx4 >> 5, j4 = idx4 & 31;
            float4 b = __ldg(b4 + j4);
            float4 v = *(float4*)(Xs + m * XLD + j4 * 4);
            v.x += b.x; v.y += b.y; v.z += b.z; v.w += b.w;
            v.x = (v.x > 0.f) ? v.x : 0.01f * v.x;
            v.y = (v.y > 0.f) ? v.y : 0.01f * v.y;
            v.z = (v.z > 0.f) ? v.z : 0.01f * v.z;
            v.w = (v.w > 0.f) ? v.w : 0.01f * v.w;
            *(float4*)(Xs + m * XLD + j4 * 4) = tf32x4(v);
        }
        __syncthreads();

        gemm128(Xs, W1s, acc, wm, wn);
        __syncthreads();
        store_acc(Xs, acc, wm, wn);
        __syncthreads();

        #pragma unroll
        for (int it = 0; it < BM * H / 4 / NTHREADS; it++) {
            int idx4 = tid + it * NTHREADS;
            int m = idx4 >> 5, j4 = idx4 & 31;
            int n = n0 + m;
            if (n < n_nodes)
                A4[(size_t)n * 32 + j4] = *(float4*)(Xs + m * XLD + j4 * 4);
        }
    }
}

// ---------------- edge kernel (persistent) ----------------
__global__ void __launch_bounds__(NTHREADS, 1)
edge_kernel(const float* __restrict__ x_src, const float* __restrict__ x_dst,
            const void* __restrict__ ei,
            const float* __restrict__ W1, const float* __restrict__ b1,
            const float* __restrict__ W2, const float* __restrict__ b2,
            float* __restrict__ out, int n_edges, int ntiles)
{
    extern __shared__ float sm[];
    float* Xs  = sm;
    float* W1s = sm + BM * XLD;
    float* W2s = sm + BM * XLD + H * WLD;
    __shared__ int s_si[BM], s_di[BM];

    const int tid = threadIdx.x;
    const int w   = tid >> 5;
    const int wm  = (w & 3) * 32;
    const int wn  = (w >> 2) * 32;
    const int is64 = g_is64;

    // weights once per CTA (W1 diff slab at koff = 2H)
    for (int idx = tid; idx < H * (H / 4); idx += NTHREADS) {
        int j = idx >> 5, k4 = idx & 31;
        float4 w1 = __ldg((const float4*)(W1 + (size_t)j * 3 * H + 2 * H) + k4);
        float4 w2 = __ldg((const float4*)(W2 + (size_t)j * H) + k4);
        *(float4*)(W1s + j * WLD + k4 * 4) = tf32x4(w1);
        *(float4*)(W2s + j * WLD + k4 * 4) = tf32x4(w2);
    }

    const float4* src4 = (const float4*)x_src;
    const float4* dst4 = (const float4*)x_dst;
    const float4* As4  = (const float4*)g_A_src;
    const float4* Ad4  = (const float4*)g_A_dst;
    const float4* b14  = (const float4*)b1;
    const float4* b24  = (const float4*)b2;
    float4*       out4 = (float4*)out;

    wmma::fragment<wmma::accumulator, 16, 16, 8, float> acc[2][2];

    for (int t = blockIdx.x; t < ntiles; t += gridDim.x) {
        const int e0 = t * BM;
        __syncthreads();   // protect Xs/s_si reuse from previous iteration

        if (tid < BM) {
            int e = e0 + tid; if (e >= n_edges) e = n_edges - 1;
            if (is64) {
                s_si[tid] = (int)((const long long*)ei)[e];
                s_di[tid] = (int)((const long long*)ei)[(size_t)n_edges + e];
            } else {
                s_si[tid] = ((const int*)ei)[e];
                s_di[tid] = ((const int*)ei)[(size_t)n_edges + e];
            }
        }
        __syncthreads();

        // gather |par - cld|
        #pragma unroll
        for (int it = 0; it < BM * H / 4 / NTHREADS; it++) {
            int idx4 = tid + it * NTHREADS;
            int m = idx4 >> 5, j4 = idx4 & 31;
            float4 p = __ldg(src4 + (size_t)s_si[m] * 32 + j4);
            float4 c = __ldg(dst4 + (size_t)s_di[m] * 32 + j4);
            float4 v;
            v.x = fabsf(p.x - c.x); v.y = fabsf(p.y - c.y);
            v.z = fabsf(p.z - c.z); v.w = fabsf(p.w - c.w);
            *(float4*)(Xs + m * XLD + j4 * 4) = tf32x4(v);
        }
        __syncthreads();

        gemm128(Xs, W1s, acc, wm, wn);
        __syncthreads();
        store_acc(Xs, acc, wm, wn);
        __syncthreads();

        // epilogue: + A_src[si] + A_dst[di] + b1, ReLU
        #pragma unroll
        for (int it = 0; it < BM * H / 4 / NTHREADS; it++) {
            int idx4 = tid + it * NTHREADS;
            int m = idx4 >> 5, j4 = idx4 & 31;
            float4 as = __ldg(As4 + (size_t)s_si[m] * 32 + j4);
            float4 ad = __ldg(Ad4 + (size_t)s_di[m] * 32 + j4);
            float4 b  = __ldg(b14 + j4);
            float4 v  = *(float4*)(Xs + m * XLD + j4 * 4);
            v.x = fmaxf(v.x + as.x + ad.x + b.x, 0.f);
            v.y = fmaxf(v.y + as.y + ad.y + b.y, 0.f);
            v.z = fmaxf(v.z + as.z + ad.z + b.z, 0.f);
            v.w = fmaxf(v.w + as.w + ad.w + b.w, 0.f);
            *(float4*)(Xs + m * XLD + j4 * 4) = tf32x4(v);
        }
        __syncthreads();

        gemm128(Xs, W2s, acc, wm, wn);
        __syncthreads();
        store_acc(Xs, acc, wm, wn);
        __syncthreads();

        // output + b2
        #pragma unroll
        for (int it = 0; it < BM * H / 4 / NTHREADS; it++) {
            int idx4 = tid + it * NTHREADS;
            int m = idx4 >> 5, j4 = idx4 & 31;
            int e = e0 + m;
            if (e < n_edges) {
                float4 b = __ldg(b24 + j4);
                float4 v = *(float4*)(Xs + m * XLD + j4 * 4);
                v.x += b.x; v.y += b.y; v.z += b.z; v.w += b.w;
                out4[(size_t)e * 32 + j4] = v;
            }
        }
    }
}

// ---------------- launch ----------------
extern "C" void kernel_launch(void* const* d_in, const int* in_sizes, int n_in,
                              void* d_out, int out_size)
{
    const float* x_src = (const float*)d_in[0];
    const float* x_dst = (const float*)d_in[1];
    const void*  ei    = d_in[2];
    const float* Wp    = (const float*)d_in[3];
    const float* bp    = (const float*)d_in[4];
    const float* Wc    = (const float*)d_in[5];
    const float* bc    = (const float*)d_in[6];
    const float* W1    = (const float*)d_in[7];
    const float* b1    = (const float*)d_in[8];
    const float* W2    = (const float*)d_in[9];
    const float* b2    = (const float*)d_in[10];

    const int n_nodes = in_sizes[0] / H;
    const int n_edges = in_sizes[2] / 2;

    static int attr_set = 0;
    if (!attr_set) {
        cudaFuncSetAttribute(node_kernel, cudaFuncAttributeMaxDynamicSharedMemorySize, SMEM_BYTES);
        cudaFuncSetAttribute(edge_kernel, cudaFuncAttributeMaxDynamicSharedMemorySize, SMEM_BYTES);
        attr_set = 1;
    }

    detect_idx_kernel<<<1, 1>>>((const int*)ei);

    float* A_src_ptr;  cudaGetSymbolAddress((void**)&A_src_ptr, g_A_src);
    float* A_dst_ptr;  cudaGetSymbolAddress((void**)&A_dst_ptr, g_A_dst);

    const int node_tiles = (n_nodes + BM - 1) / BM;
    const int ngrid = node_tiles < NSM ? node_tiles : NSM;
    node_kernel<<<ngrid, NTHREADS, SMEM_BYTES>>>(x_src, Wp, bp, W1, 0, A_src_ptr, n_nodes, node_tiles);
    node_kernel<<<ngrid, NTHREADS, SMEM_BYTES>>>(x_dst, Wc, bc, W1, H, A_dst_ptr, n_nodes, node_tiles);

    const int edge_tiles = (n_edges + BM - 1) / BM;
    const int egrid = edge_tiles < NSM ? edge_tiles : NSM;
    edge_kernel<<<egrid, NTHREADS, SMEM_BYTES>>>(
        x_src, x_dst, ei, W1, b1, W2, b2, (float*)d_out, n_edges, edge_tiles);
}

// round 3
// speedup vs baseline: 1.7968x; 1.0470x over previous
#include <cuda_runtime.h>
#include <mma.h>
#include <math.h>

using namespace nvcuda;

#define H        128
#define BM       128
#define XLD      132
#define WLD      132
#define NTHREADS 512
#define MAX_NODES 100000
#define NSM      152
#define SMEM_BYTES ((BM * XLD + 2 * H * WLD) * 4)

// ---------------- scratch ----------------
__device__ int   g_is64;
__device__ float g_A_src[(size_t)MAX_NODES * H];
__device__ float g_A_dst[(size_t)MAX_NODES * H];

// ---------------- int32/int64 detection ----------------
__global__ void detect_idx_kernel(const int* __restrict__ ei)
{
    int allz = 1;
    #pragma unroll
    for (int i = 1; i < 128; i += 2)
        if (ei[i] != 0) { allz = 0; break; }
    g_is64 = allz;
}

// ---------------- helpers ----------------
__device__ __forceinline__ void pf_l2(const void* p)
{
    asm volatile("prefetch.global.L2 [%0];" :: "l"(p));
}

__device__ __forceinline__ float4 tf32x4(float4 v)
{
    v.x = wmma::__float_to_tf32(v.x);
    v.y = wmma::__float_to_tf32(v.y);
    v.z = wmma::__float_to_tf32(v.z);
    v.w = wmma::__float_to_tf32(v.w);
    return v;
}

// 16 warps: warp w -> M rows [wm,wm+32), N cols [wn,wn+32)
__device__ __forceinline__ void gemm128(
    const float* __restrict__ Xs, const float* __restrict__ Ws,
    wmma::fragment<wmma::accumulator, 16, 16, 8, float> (&acc)[2][2],
    int wm, int wn)
{
    #pragma unroll
    for (int i = 0; i < 2; i++)
        #pragma unroll
        for (int j = 0; j < 2; j++)
            wmma::fill_fragment(acc[i][j], 0.0f);

    #pragma unroll
    for (int k0 = 0; k0 < H; k0 += 8) {
        wmma::fragment<wmma::matrix_a, 16, 16, 8, wmma::precision::tf32, wmma::row_major> a[2];
        wmma::fragment<wmma::matrix_b, 16, 16, 8, wmma::precision::tf32, wmma::col_major> b[2];
        #pragma unroll
        for (int i = 0; i < 2; i++)
            wmma::load_matrix_sync(a[i], Xs + (wm + i * 16) * XLD + k0, XLD);
        #pragma unroll
        for (int j = 0; j < 2; j++)
            wmma::load_matrix_sync(b[j], Ws + (wn + j * 16) * WLD + k0, WLD);
        #pragma unroll
        for (int i = 0; i < 2; i++)
            #pragma unroll
            for (int j = 0; j < 2; j++)
                wmma::mma_sync(acc[i][j], a[i], b[j], acc[i][j]);
    }
}

__device__ __forceinline__ void store_acc(
    float* __restrict__ Xs,
    wmma::fragment<wmma::accumulator, 16, 16, 8, float> (&acc)[2][2],
    int wm, int wn)
{
    #pragma unroll
    for (int i = 0; i < 2; i++)
        #pragma unroll
        for (int j = 0; j < 2; j++)
            wmma::store_matrix_sync(Xs + (wm + i * 16) * XLD + wn + j * 16,
                                    acc[i][j], XLD, wmma::mem_row_major);
}

// ---------------- node precompute: single wave, both halves per CTA ----------------
// A[n] = (leakyrelu(x @ Wenc^T + benc)) @ W1slab^T
__global__ void __launch_bounds__(NTHREADS, 1)
node_kernel(const float* __restrict__ x_src, const float* __restrict__ x_dst,
            const float* __restrict__ Wp, const float* __restrict__ bp,
            const float* __restrict__ Wc, const float* __restrict__ bc,
            const float* __restrict__ W1,
            float* __restrict__ A_src, float* __restrict__ A_dst,
            int n_nodes, int ntiles)
{
    extern __shared__ float sm[];
    float* Xs  = sm;
    float* Ws  = sm + BM * XLD;
    float* W1s = Ws + H * WLD;

    const int tid  = threadIdx.x;
    const int lane = tid & 31;
    const int w    = tid >> 5;
    const int wm   = (w & 3) * 32;
    const int wn   = (w >> 2) * 32;

    wmma::fragment<wmma::accumulator, 16, 16, 8, float> acc[2][2];

    for (int half = 0; half < 2; half++) {
        const float* x    = half ? x_dst : x_src;
        const float* Wenc = half ? Wc    : Wp;
        const float* benc = half ? bc    : bp;
        const int    koff = half ? H     : 0;
        float*       Aout = half ? A_dst : A_src;

        __syncthreads();   // previous half's Xs consumers done
        // load this half's weights
        for (int idx = tid; idx < H * 32; idx += NTHREADS) {
            int j = idx >> 5, k4 = idx & 31;
            float4 we = __ldg((const float4*)(Wenc + (size_t)j * H) + k4);
            float4 w1 = __ldg((const float4*)(W1 + (size_t)j * 3 * H + koff) + k4);
            *(float4*)(Ws  + j * WLD + k4 * 4) = tf32x4(we);
            *(float4*)(W1s + j * WLD + k4 * 4) = tf32x4(w1);
        }
        float4 ber = __ldg((const float4*)benc + lane);

        const float4* x4 = (const float4*)x;
        float4*       A4 = (float4*)Aout;

        __syncthreads();

        for (int t = blockIdx.x; t < ntiles; t += gridDim.x) {
            const int n0 = t * BM;

            // load X tile; prefetch next tile's rows into L2
            #pragma unroll
            for (int it = 0; it < 8; it++) {
                int m = (tid >> 5) + it * 16;
                int n = n0 + m; if (n >= n_nodes) n = n_nodes - 1;
                float4 v = __ldg(x4 + (size_t)n * 32 + lane);
                *(float4*)(Xs + m * XLD + lane * 4) = tf32x4(v);
            }
            {
                int tn = t + gridDim.x;
                if (tn < ntiles && (lane & 7) == 0) {
                    int n0n = tn * BM;
                    #pragma unroll
                    for (int it = 0; it < 8; it++) {
                        int m = (tid >> 5) + it * 16;
                        int n = n0n + m; if (n >= n_nodes) n = n_nodes - 1;
                        pf_l2(x4 + (size_t)n * 32 + lane);
                    }
                }
            }
            __syncthreads();

            gemm128(Xs, Ws, acc, wm, wn);
            __syncthreads();
            store_acc(Xs, acc, wm, wn);
            __syncthreads();

            // LeakyReLU epilogue
            #pragma unroll
            for (int it = 0; it < 8; it++) {
                int m = (tid >> 5) + it * 16;
                float4 v = *(float4*)(Xs + m * XLD + lane * 4);
                v.x += ber.x; v.y += ber.y; v.z += ber.z; v.w += ber.w;
                v.x = (v.x > 0.f) ? v.x : 0.01f * v.x;
                v.y = (v.y > 0.f) ? v.y : 0.01f * v.y;
                v.z = (v.z > 0.f) ? v.z : 0.01f * v.z;
                v.w = (v.w > 0.f) ? v.w : 0.01f * v.w;
                *(float4*)(Xs + m * XLD + lane * 4) = tf32x4(v);
            }
            __syncthreads();

            gemm128(Xs, W1s, acc, wm, wn);
            __syncthreads();
            store_acc(Xs, acc, wm, wn);
            __syncthreads();

            #pragma unroll
            for (int it = 0; it < 8; it++) {
                int m = (tid >> 5) + it * 16;
                int n = n0 + m;
                if (n < n_nodes)
                    A4[(size_t)n * 32 + lane] = *(float4*)(Xs + m * XLD + lane * 4);
            }
            __syncthreads();
        }
    }
}

// ---------------- edge kernel (persistent, L2-prefetch pipelined) ----------------
__global__ void __launch_bounds__(NTHREADS, 1)
edge_kernel(const float* __restrict__ x_src, const float* __restrict__ x_dst,
            const void* __restrict__ ei,
            const float* __restrict__ W1, const float* __restrict__ b1,
            const float* __restrict__ W2, const float* __restrict__ b2,
            float* __restrict__ out, int n_edges, int ntiles)
{
    extern __shared__ float sm[];
    float* Xs  = sm;
    float* W1s = sm + BM * XLD;
    float* W2s = W1s + H * WLD;
    __shared__ int s_si[2][BM], s_di[2][BM];

    const int tid  = threadIdx.x;
    const int lane = tid & 31;
    const int w    = tid >> 5;
    const int wm   = (w & 3) * 32;
    const int wn   = (w >> 2) * 32;
    const int is64 = g_is64;

    for (int idx = tid; idx < H * 32; idx += NTHREADS) {
        int j = idx >> 5, k4 = idx & 31;
        float4 w1 = __ldg((const float4*)(W1 + (size_t)j * 3 * H + 2 * H) + k4);
        float4 w2 = __ldg((const float4*)(W2 + (size_t)j * H) + k4);
        *(float4*)(W1s + j * WLD + k4 * 4) = tf32x4(w1);
        *(float4*)(W2s + j * WLD + k4 * 4) = tf32x4(w2);
    }
    float4 b1r = __ldg((const float4*)b1 + lane);
    float4 b2r = __ldg((const float4*)b2 + lane);

    const float4* src4 = (const float4*)x_src;
    const float4* dst4 = (const float4*)x_dst;
    const float4* As4  = (const float4*)g_A_src;
    const float4* Ad4  = (const float4*)g_A_dst;
    float4*       out4 = (float4*)out;

    // first tile's indices
    if (blockIdx.x < ntiles && tid < BM) {
        int e = blockIdx.x * BM + tid; if (e >= n_edges) e = n_edges - 1;
        if (is64) {
            s_si[0][tid] = (int)((const long long*)ei)[e];
            s_di[0][tid] = (int)((const long long*)ei)[(size_t)n_edges + e];
        } else {
            s_si[0][tid] = ((const int*)ei)[e];
            s_di[0][tid] = ((const int*)ei)[(size_t)n_edges + e];
        }
    }
    __syncthreads();

    wmma::fragment<wmma::accumulator, 16, 16, 8, float> acc[2][2];
    int buf = 0;

    for (int tt = blockIdx.x; tt < ntiles; tt += gridDim.x) {
        const int nbuf = buf ^ 1;
        const int tn   = tt + gridDim.x;

        // gather |par - cld| ; prefetch this tile's A lines (consumed after GEMM1)
        #pragma unroll
        for (int it = 0; it < 8; it++) {
            int m  = (tid >> 5) + it * 16;
            int si = s_si[buf][m], di = s_di[buf][m];
            float4 p = __ldg(src4 + (size_t)si * 32 + lane);
            float4 c = __ldg(dst4 + (size_t)di * 32 + lane);
            if ((lane & 7) == 0) {
                pf_l2(As4 + (size_t)si * 32 + lane);
                pf_l2(Ad4 + (size_t)di * 32 + lane);
            }
            float4 v;
            v.x = fabsf(p.x - c.x); v.y = fabsf(p.y - c.y);
            v.z = fabsf(p.z - c.z); v.w = fabsf(p.w - c.w);
            *(float4*)(Xs + m * XLD + lane * 4) = tf32x4(v);
        }
        // next tile's indices into the other buffer
        if (tn < ntiles && tid < BM) {
            int e = tn * BM + tid; if (e >= n_edges) e = n_edges - 1;
            if (is64) {
                s_si[nbuf][tid] = (int)((const long long*)ei)[e];
                s_di[nbuf][tid] = (int)((const long long*)ei)[(size_t)n_edges + e];
            } else {
                s_si[nbuf][tid] = ((const int*)ei)[e];
                s_di[nbuf][tid] = ((const int*)ei)[(size_t)n_edges + e];
            }
        }
        __syncthreads();

        // prefetch next tile's x gather lines (they have GEMM1+epi+GEMM2 to land)
        if (tn < ntiles && (lane & 7) == 0) {
            #pragma unroll
            for (int it = 0; it < 8; it++) {
                int m = (tid >> 5) + it * 16;
                pf_l2(src4 + (size_t)s_si[nbuf][m] * 32 + lane);
                pf_l2(dst4 + (size_t)s_di[nbuf][m] * 32 + lane);
            }
        }

        gemm128(Xs, W1s, acc, wm, wn);
        __syncthreads();
        store_acc(Xs, acc, wm, wn);
        __syncthreads();

        // epilogue: + A_src[si] + A_dst[di] + b1, ReLU  (A lines prefetched)
        #pragma unroll
        for (int it = 0; it < 8; it++) {
            int m  = (tid >> 5) + it * 16;
            int si = s_si[buf][m], di = s_di[buf][m];
            float4 as = __ldg(As4 + (size_t)si * 32 + lane);
            float4 ad = __ldg(Ad4 + (size_t)di * 32 + lane);
            float4 v  = *(float4*)(Xs + m * XLD + lane * 4);
            v.x = fmaxf(v.x + as.x + ad.x + b1r.x, 0.f);
            v.y = fmaxf(v.y + as.y + ad.y + b1r.y, 0.f);
            v.z = fmaxf(v.z + as.z + ad.z + b1r.z, 0.f);
            v.w = fmaxf(v.w + as.w + ad.w + b1r.w, 0.f);
            *(float4*)(Xs + m * XLD + lane * 4) = tf32x4(v);
        }
        __syncthreads();

        gemm128(Xs, W2s, acc, wm, wn);
        __syncthreads();
        store_acc(Xs, acc, wm, wn);
        __syncthreads();

        // output + b2 (streaming stores: keep L2 for the gather working set)
        #pragma unroll
        for (int it = 0; it < 8; it++) {
            int m = (tid >> 5) + it * 16;
            int e = tt * BM + m;
            if (e < n_edges) {
                float4 v = *(float4*)(Xs + m * XLD + lane * 4);
                v.x += b2r.x; v.y += b2r.y; v.z += b2r.z; v.w += b2r.w;
                __stcs(out4 + (size_t)e * 32 + lane, v);
            }
        }
        __syncthreads();   // protect Xs before next gather
        buf = nbuf;
    }
}

// ---------------- launch ----------------
extern "C" void kernel_launch(void* const* d_in, const int* in_sizes, int n_in,
                              void* d_out, int out_size)
{
    const float* x_src = (const float*)d_in[0];
    const float* x_dst = (const float*)d_in[1];
    const void*  ei    = d_in[2];
    const float* Wp    = (const float*)d_in[3];
    const float* bp    = (const float*)d_in[4];
    const float* Wc    = (const float*)d_in[5];
    const float* bc    = (const float*)d_in[6];
    const float* W1    = (const float*)d_in[7];
    const float* b1    = (const float*)d_in[8];
    const float* W2    = (const float*)d_in[9];
    const float* b2    = (const float*)d_in[10];

    const int n_nodes = in_sizes[0] / H;
    const int n_edges = in_sizes[2] / 2;

    static int attr_set = 0;
    if (!attr_set) {
        cudaFuncSetAttribute(node_kernel, cudaFuncAttributeMaxDynamicSharedMemorySize, SMEM_BYTES);
        cudaFuncSetAttribute(edge_kernel, cudaFuncAttributeMaxDynamicSharedMemorySize, SMEM_BYTES);
        attr_set = 1;
    }

    detect_idx_kernel<<<1, 1>>>((const int*)ei);

    float* A_src_ptr;  cudaGetSymbolAddress((void**)&A_src_ptr, g_A_src);
    float* A_dst_ptr;  cudaGetSymbolAddress((void**)&A_dst_ptr, g_A_dst);

    const int node_tiles = (n_nodes + BM - 1) / BM;
    const int ngrid = node_tiles < NSM ? node_tiles : NSM;
    node_kernel<<<ngrid, NTHREADS, SMEM_BYTES>>>(
        x_src, x_dst, Wp, bp, Wc, bc, W1, A_src_ptr, A_dst_ptr, n_nodes, node_tiles);

    const int edge_tiles = (n_edges + BM - 1) / BM;
    const int egrid = edge_tiles < NSM ? edge_tiles : NSM;
    edge_kernel<<<egrid, NTHREADS, SMEM_BYTES>>>(
        x_src, x_dst, ei, W1, b1, W2, b2, (float*)d_out, n_edges, edge_tiles);
}

// round 5
// speedup vs baseline: 2.1724x; 1.2090x over previous
#include <cuda_runtime.h>
#include <cstdint>
#include <mma.h>
#include <math.h>

using namespace nvcuda;

#define H        128
#define BM       64       // rows per tile (double-buffered)
#define XLD      132      // padded leading dim (floats)
#define WLD      132
#define NTHREADS 512      // 16 warps
#define NSM      152
// smem: 2 X buffers + 2 weight matrices
#define SMEM_BYTES ((2 * BM * XLD + 2 * H * WLD) * 4)

// ---------------- scratch ----------------
#define MAX_NODES 100000
__device__ int   g_is64;
__device__ float g_A_src[(size_t)MAX_NODES * H];
__device__ float g_A_dst[(size_t)MAX_NODES * H];

// ---------------- int32/int64 detection (parallel) ----------------
__global__ void detect_idx_kernel(const int* __restrict__ ei)
{
    int odd = ei[threadIdx.x * 2 + 1];
    unsigned any = __ballot_sync(0xFFFFFFFFu, odd != 0);
    __shared__ unsigned s[2];
    if ((threadIdx.x & 31) == 0) s[threadIdx.x >> 5] = any;
    __syncthreads();
    if (threadIdx.x == 0) g_is64 = (s[0] | s[1]) ? 0 : 1;
}

// ---------------- helpers ----------------
__device__ __forceinline__ void pf_l2(const void* p)
{
    asm volatile("prefetch.global.L2 [%0];" :: "l"(p));
}

__device__ __forceinline__ void cp16(unsigned dst_smem, const void* src)
{
    asm volatile("cp.async.cg.shared.global [%0], [%1], 16;" :: "r"(dst_smem), "l"(src));
}
__device__ __forceinline__ void cp_commit()
{
    asm volatile("cp.async.commit_group;");
}
__device__ __forceinline__ void cp_wait_all()
{
    asm volatile("cp.async.wait_group 0;");
}

__device__ __forceinline__ float4 tf32x4(float4 v)
{
    v.x = wmma::__float_to_tf32(v.x);
    v.y = wmma::__float_to_tf32(v.y);
    v.z = wmma::__float_to_tf32(v.z);
    v.w = wmma::__float_to_tf32(v.w);
    return v;
}

// 16 warps on a 64x128 tile: warp w -> rows [wm,wm+16), cols [wn,wn+32)
__device__ __forceinline__ void gemm64(
    const float* __restrict__ Xs, const float* __restrict__ Ws,
    wmma::fragment<wmma::accumulator, 16, 16, 8, float> (&acc)[2],
    int wm, int wn)
{
    #pragma unroll
    for (int j = 0; j < 2; j++)
        wmma::fill_fragment(acc[j], 0.0f);

    #pragma unroll
    for (int k0 = 0; k0 < H; k0 += 8) {
        wmma::fragment<wmma::matrix_a, 16, 16, 8, wmma::precision::tf32, wmma::row_major> a;
        wmma::fragment<wmma::matrix_b, 16, 16, 8, wmma::precision::tf32, wmma::col_major> b[2];
        wmma::load_matrix_sync(a, Xs + wm * XLD + k0, XLD);
        #pragma unroll
        for (int j = 0; j < 2; j++)
            wmma::load_matrix_sync(b[j], Ws + (wn + j * 16) * WLD + k0, WLD);
        #pragma unroll
        for (int j = 0; j < 2; j++)
            wmma::mma_sync(acc[j], a, b[j], acc[j]);
    }
}

__device__ __forceinline__ void store_acc64(
    float* __restrict__ Xs,
    wmma::fragment<wmma::accumulator, 16, 16, 8, float> (&acc)[2],
    int wm, int wn)
{
    #pragma unroll
    for (int j = 0; j < 2; j++)
        wmma::store_matrix_sync(Xs + wm * XLD + wn + j * 16, acc[j], XLD,
                                wmma::mem_row_major);
}

// ---------------- node precompute (persistent, cp.async pipelined) ----------------
// A[n] = (leakyrelu(x @ Wenc^T + benc)) @ W1slab^T
__global__ void __launch_bounds__(NTHREADS, 1)
node_kernel(const float* __restrict__ x_src, const float* __restrict__ x_dst,
            const float* __restrict__ Wp, const float* __restrict__ bp,
            const float* __restrict__ Wc, const float* __restrict__ bc,
            const float* __restrict__ W1,
            float* __restrict__ A_src, float* __restrict__ A_dst,
            int n_nodes, int ntiles)
{
    extern __shared__ float sm[];
    float* X[2] = { sm, sm + BM * XLD };
    float* Ws   = sm + 2 * BM * XLD;
    float* W1s  = Ws + H * WLD;

    const int tid  = threadIdx.x;
    const int lane = tid & 31;
    const int w    = tid >> 5;
    const int wm   = (w & 3) * 16;
    const int wn   = (w >> 2) * 32;

    unsigned xb[2];
    xb[0] = (unsigned)__cvta_generic_to_shared(X[0]);
    xb[1] = (unsigned)__cvta_generic_to_shared(X[1]);

    wmma::fragment<wmma::accumulator, 16, 16, 8, float> acc[2];

    for (int half = 0; half < 2; half++) {
        const float* x    = half ? x_dst : x_src;
        const float* Wenc = half ? Wc    : Wp;
        const float* benc = half ? bc    : bp;
        const int    koff = half ? H     : 0;
        float*       Aout = half ? A_dst : A_src;

        __syncthreads();   // previous half fully done
        for (int idx = tid; idx < H * 32; idx += NTHREADS) {
            int j = idx >> 5, k4 = idx & 31;
            float4 we = __ldg((const float4*)(Wenc + (size_t)j * H) + k4);
            float4 w1 = __ldg((const float4*)(W1 + (size_t)j * 3 * H + koff) + k4);
            *(float4*)(Ws  + j * WLD + k4 * 4) = tf32x4(we);
            *(float4*)(W1s + j * WLD + k4 * 4) = tf32x4(w1);
        }
        float4 ber = __ldg((const float4*)benc + lane);
        __syncthreads();

        // prologue: stage first tile
        int t0 = blockIdx.x;
        if (t0 < ntiles) {
            #pragma unroll
            for (int it = 0; it < 4; it++) {
                int ch = tid + it * NTHREADS;          // 2048 16B chunks
                int m = ch >> 5, off = ch & 31;
                int n = t0 * BM + m; if (n >= n_nodes) n = n_nodes - 1;
                cp16(xb[0] + (unsigned)(m * XLD + off * 4) * 4,
                     x + (size_t)n * H + off * 4);
            }
            cp_commit();
        }

        int lt = 0;
        for (int t = blockIdx.x; t < ntiles; t += gridDim.x, lt++) {
            const int buf = lt & 1, nbuf = buf ^ 1;
            const int tn  = t + gridDim.x;
            float* Xb = X[buf];

            cp_wait_all();
            __syncthreads();

            // tf32 convert pass (in place)
            #pragma unroll
            for (int it = 0; it < 4; it++) {
                int m = w + it * 16;
                float4* p = (float4*)(Xb + m * XLD + lane * 4);
                *p = tf32x4(*p);
            }

            // stage next tile into the other buffer
            if (tn < ntiles) {
                #pragma unroll
                for (int it = 0; it < 4; it++) {
                    int ch = tid + it * NTHREADS;
                    int m = ch >> 5, off = ch & 31;
                    int n = tn * BM + m; if (n >= n_nodes) n = n_nodes - 1;
                    cp16(xb[nbuf] + (unsigned)(m * XLD + off * 4) * 4,
                         x + (size_t)n * H + off * 4);
                }
                cp_commit();
            }
            __syncthreads();

            gemm64(Xb, Ws, acc, wm, wn);
            __syncthreads();
            store_acc64(Xb, acc, wm, wn);
            __syncthreads();

            // bias + LeakyReLU
            #pragma unroll
            for (int it = 0; it < 4; it++) {
                int m = w + it * 16;
                float4 v = *(float4*)(Xb + m * XLD + lane * 4);
                v.x += ber.x; v.y += ber.y; v.z += ber.z; v.w += ber.w;
                v.x = (v.x > 0.f) ? v.x : 0.01f * v.x;
                v.y = (v.y > 0.f) ? v.y : 0.01f * v.y;
                v.z = (v.z > 0.f) ? v.z : 0.01f * v.z;
                v.w = (v.w > 0.f) ? v.w : 0.01f * v.w;
                *(float4*)(Xb + m * XLD + lane * 4) = tf32x4(v);
            }
            __syncthreads();

            gemm64(Xb, W1s, acc, wm, wn);
            __syncthreads();
            store_acc64(Xb, acc, wm, wn);
            __syncthreads();

            #pragma unroll
            for (int it = 0; it < 4; it++) {
                int m = w + it * 16;
                int n = t * BM + m;
                if (n < n_nodes)
                    *((float4*)(Aout + (size_t)n * H) + lane) =
                        *(float4*)(Xb + m * XLD + lane * 4);
            }
            __syncthreads();
        }
    }
}

// ---------------- edge kernel (persistent, cp.async pipelined gathers) ----------------
__global__ void __launch_bounds__(NTHREADS, 1)
edge_kernel(const float* __restrict__ x_src, const float* __restrict__ x_dst,
            const void* __restrict__ ei,
            const float* __restrict__ W1, const float* __restrict__ b1,
            const float* __restrict__ W2, const float* __restrict__ b2,
            float* __restrict__ out, int n_edges, int ntiles)
{
    extern __shared__ float sm[];
    float* X[2] = { sm, sm + BM * XLD };
    float* W1s  = sm + 2 * BM * XLD;
    float* W2s  = W1s + H * WLD;
    __shared__ int s_si[2][BM], s_di[2][BM];

    const int tid  = threadIdx.x;
    const int lane = tid & 31;
    const int w    = tid >> 5;
    const int wm   = (w & 3) * 16;
    const int wn   = (w >> 2) * 32;
    const int is64 = g_is64;

    unsigned xb[2];
    xb[0] = (unsigned)__cvta_generic_to_shared(X[0]);
    xb[1] = (unsigned)__cvta_generic_to_shared(X[1]);

    for (int idx = tid; idx < H * 32; idx += NTHREADS) {
        int j = idx >> 5, k4 = idx & 31;
        float4 w1 = __ldg((const float4*)(W1 + (size_t)j * 3 * H + 2 * H) + k4);
        float4 w2 = __ldg((const float4*)(W2 + (size_t)j * H) + k4);
        *(float4*)(W1s + j * WLD + k4 * 4) = tf32x4(w1);
        *(float4*)(W2s + j * WLD + k4 * 4) = tf32x4(w2);
    }
    float4 b1r = __ldg((const float4*)b1 + lane);
    float4 b2r = __ldg((const float4*)b2 + lane);

    const float4* dst4 = (const float4*)x_dst;
    const float4* As4  = (const float4*)g_A_src;
    const float4* Ad4  = (const float4*)g_A_dst;
    float4*       out4 = (float4*)out;

    // prologue: indices + parent cp.async for first tile
    if (blockIdx.x < ntiles && tid < BM) {
        int e = blockIdx.x * BM + tid; if (e >= n_edges) e = n_edges - 1;
        if (is64) {
            s_si[0][tid] = (int)((const long long*)ei)[e];
            s_di[0][tid] = (int)((const long long*)ei)[(size_t)n_edges + e];
        } else {
            s_si[0][tid] = ((const int*)ei)[e];
            s_di[0][tid] = ((const int*)ei)[(size_t)n_edges + e];
        }
    }
    __syncthreads();
    if (blockIdx.x < ntiles) {
        #pragma unroll
        for (int it = 0; it < 4; it++) {
            int ch = tid + it * NTHREADS;
            int m = ch >> 5, off = ch & 31;
            cp16(xb[0] + (unsigned)(m * XLD + off * 4) * 4,
                 x_src + (size_t)s_si[0][m] * H + off * 4);
        }
        cp_commit();
    }

    wmma::fragment<wmma::accumulator, 16, 16, 8, float> acc[2];

    int lt = 0;
    for (int t = blockIdx.x; t < ntiles; t += gridDim.x, lt++) {
        const int buf = lt & 1, nbuf = buf ^ 1;
        const int tn  = t + gridDim.x;
        float* Xb = X[buf];

        // next tile's indices (visible after the sync below)
        if (tn < ntiles && tid < BM) {
            int e = tn * BM + tid; if (e >= n_edges) e = n_edges - 1;
            if (is64) {
                s_si[nbuf][tid] = (int)((const long long*)ei)[e];
                s_di[nbuf][tid] = (int)((const long long*)ei)[(size_t)n_edges + e];
            } else {
                s_si[nbuf][tid] = ((const int*)ei)[e];
                s_di[nbuf][tid] = ((const int*)ei)[(size_t)n_edges + e];
            }
        }

        cp_wait_all();
        __syncthreads();

        // convert pass: diff = |p - c| (p staged in smem, c direct, L2-prefetched)
        // also prefetch this tile's A lines (consumed after GEMM1)
        #pragma unroll
        for (int it = 0; it < 4; it++) {
            int m  = w + it * 16;
            int si = s_si[buf][m], di = s_di[buf][m];
            float4 p = *(float4*)(Xb + m * XLD + lane * 4);
            float4 c = __ldg(dst4 + (size_t)di * 32 + lane);
            if ((lane & 7) == 0) {
                pf_l2(As4 + (size_t)si * 32 + lane);
                pf_l2(Ad4 + (size_t)di * 32 + lane);
            }
            float4 v;
            v.x = fabsf(p.x - c.x); v.y = fabsf(p.y - c.y);
            v.z = fabsf(p.z - c.z); v.w = fabsf(p.w - c.w);
            *(float4*)(Xb + m * XLD + lane * 4) = tf32x4(v);
        }

        // stage next tile's parent rows; prefetch next child rows
        if (tn < ntiles) {
            #pragma unroll
            for (int it = 0; it < 4; it++) {
                int ch = tid + it * NTHREADS;
                int m = ch >> 5, off = ch & 31;
                cp16(xb[nbuf] + (unsigned)(m * XLD + off * 4) * 4,
                     x_src + (size_t)s_si[nbuf][m] * H + off * 4);
            }
            cp_commit();
            if ((lane & 7) == 0) {
                #pragma unroll
                for (int it = 0; it < 4; it++) {
                    int m = w + it * 16;
                    pf_l2(dst4 + (size_t)s_di[nbuf][m] * 32 + lane);
                }
            }
        }
        __syncthreads();

        gemm64(Xb, W1s, acc, wm, wn);
        __syncthreads();
        store_acc64(Xb, acc, wm, wn);
        __syncthreads();

        // epilogue: + A_src + A_dst + b1, ReLU
        #pragma unroll
        for (int it = 0; it < 4; it++) {
            int m  = w + it * 16;
            int si = s_si[buf][m], di = s_di[buf][m];
            float4 as = __ldg(As4 + (size_t)si * 32 + lane);
            float4 ad = __ldg(Ad4 + (size_t)di * 32 + lane);
            float4 v  = *(float4*)(Xb + m * XLD + lane * 4);
            v.x = fmaxf(v.x + as.x + ad.x + b1r.x, 0.f);
            v.y = fmaxf(v.y + as.y + ad.y + b1r.y, 0.f);
            v.z = fmaxf(v.z + as.z + ad.z + b1r.z, 0.f);
            v.w = fmaxf(v.w + as.w + ad.w + b1r.w, 0.f);
            *(float4*)(Xb + m * XLD + lane * 4) = tf32x4(v);
        }
        __syncthreads();

        gemm64(Xb, W2s, acc, wm, wn);
        __syncthreads();
        store_acc64(Xb, acc, wm, wn);
        __syncthreads();

        // output + b2 (streaming stores)
        #pragma unroll
        for (int it = 0; it < 4; it++) {
            int m = w + it * 16;
            int e = t * BM + m;
            if (e < n_edges) {
                float4 v = *(float4*)(Xb + m * XLD + lane * 4);
                v.x += b2r.x; v.y += b2r.y; v.z += b2r.z; v.w += b2r.w;
                __stcs(out4 + (size_t)e * 32 + lane, v);
            }
        }
        __syncthreads();
    }
}

// ---------------- launch ----------------
extern "C" void kernel_launch(void* const* d_in, const int* in_sizes, int n_in,
                              void* d_out, int out_size)
{
    const float* x_src = (const float*)d_in[0];
    const float* x_dst = (const float*)d_in[1];
    const void*  ei    = d_in[2];
    const float* Wp    = (const float*)d_in[3];
    const float* bp    = (const float*)d_in[4];
    const float* Wc    = (const float*)d_in[5];
    const float* bc    = (const float*)d_in[6];
    const float* W1    = (const float*)d_in[7];
    const float* b1    = (const float*)d_in[8];
    const float* W2    = (const float*)d_in[9];
    const float* b2    = (const float*)d_in[10];

    const int n_nodes = in_sizes[0] / H;
    const int n_edges = in_sizes[2] / 2;

    static int attr_set = 0;
    if (!attr_set) {
        cudaFuncSetAttribute(node_kernel, cudaFuncAttributeMaxDynamicSharedMemorySize, SMEM_BYTES);
        cudaFuncSetAttribute(edge_kernel, cudaFuncAttributeMaxDynamicSharedMemorySize, SMEM_BYTES);
        attr_set = 1;
    }

    detect_idx_kernel<<<1, 64>>>((const int*)ei);

    float* A_src_ptr;  cudaGetSymbolAddress((void**)&A_src_ptr, g_A_src);
    float* A_dst_ptr;  cudaGetSymbolAddress((void**)&A_dst_ptr, g_A_dst);

    const int node_tiles = (n_nodes + BM - 1) / BM;
    const int ngrid = node_tiles < NSM ? node_tiles : NSM;
    node_kernel<<<ngrid, NTHREADS, SMEM_BYTES>>>(
        x_src, x_dst, Wp, bp, Wc, bc, W1, A_src_ptr, A_dst_ptr, n_nodes, node_tiles);

    const int edge_tiles = (n_edges + BM - 1) / BM;
    const int egrid = edge_tiles < NSM ? edge_tiles : NSM;
    edge_kernel<<<egrid, NTHREADS, SMEM_BYTES>>>(
        x_src, x_dst, ei, W1, b1, W2, b2, (float*)d_out, n_edges, edge_tiles);
}